// round 9
// baseline (speedup 1.0000x reference)
#include <cuda_runtime.h>
#include <math.h>

// Problem constants
#define BB 4
#define NN 2048
#define DD 1024
#define EE 16
#define CC 256
#define BE (BB*EE)                 // 64 (b,e) pairs
#define DISP_ELEMS (BB*NN*EE*CC)   // 33554432 floats per output tensor

#define FLT_MIN_NORMAL 1.17549435e-38f

#define GRID_BLOCKS 132            // <= SM count -> all blocks co-resident (software sync safe)
#define SORT_BLOCKS 64             // blocks 0..63: logits + sort + scatter for (b,e)=bid
#define THREADS 1024

#define OUT_F4   (2 * DISP_ELEMS / 4)   // 16777216 float4 covering both tensors
#define CHUNK_F4 16384                  // 256 KB zero-fill work unit (16 f4/thread)
#define NCHUNK   (OUT_F4 / CHUNK_F4)    // 1024 chunks

typedef unsigned long long u64;

// Scratch + sync state (no allocations allowed -> __device__ globals)
__device__ float    g_logits[BE * NN];  // [(b*EE+e)*NN + n]
__device__ unsigned g_bar_b[BB];        // per-batch logits barrier (16 arrivals each)
__device__ unsigned g_ticket;           // zero-fill work-stealing ticket
__device__ unsigned g_zdone;            // blocks finished with zero-fill

// ---------------------------------------------------------------------------
// K0: reset sync counters (every launch; deterministic, graph-capturable)
// ---------------------------------------------------------------------------
__global__ void init_kernel()
{
    if (threadIdx.x < BB) g_bar_b[threadIdx.x] = 0u;
    if (threadIdx.x == 0) { g_ticket = 0u; g_zdone = 0u; }
}

// ---------------------------------------------------------------------------
// Zero-fill: atomic-ticket chunks of 16384 float4. All zeros -> output is
// deterministic regardless of which block writes which chunk.
// ---------------------------------------------------------------------------
__device__ __forceinline__ void zfill_loop(float4* o4, unsigned* s_chunk)
{
    const float4 z = make_float4(0.f, 0.f, 0.f, 0.f);
    for (;;) {
        if (threadIdx.x == 0) *s_chunk = atomicAdd(&g_ticket, 1u);
        __syncthreads();
        const unsigned c = *s_chunk;
        __syncthreads();                       // readers done before next overwrite
        if (c >= NCHUNK) break;
        size_t base = (size_t)c * CHUNK_F4 + threadIdx.x;
#pragma unroll
        for (int k = 0; k < 16; ++k)
            __stcs(o4 + base + k * 1024, z);
    }
}

// ---------------------------------------------------------------------------
// K1: single co-resident kernel.
//   blocks [0,64):    logits (warp-per-token, numerics identical to prior
//                     passing kernel) -> per-batch barrier -> softmax +
//                     register bitonic sort -> join zfill -> wait zfill done
//                     -> scatter hit slots.
//   blocks [64,132):  zero-fill from t=0 (DRAM-bound long pole).
// ---------------------------------------------------------------------------
__global__ void __launch_bounds__(THREADS, 1)
moe_kernel(const float* __restrict__ key,
           const float* __restrict__ query,
           const float* __restrict__ temp,
           float* __restrict__ out)
{
    __shared__ float    aff[NN];          // 8 KB
    __shared__ u64      xbuf[2][NN];      // 32 KB double-buffered sort exchange
    __shared__ float    red[32];
    __shared__ unsigned s_chunk;

    const int tid = threadIdx.x;
    const int bid = blockIdx.x;
    float4* o4 = reinterpret_cast<float4*>(out);

    // ======================= pure zero-fill blocks =========================
    if (bid >= SORT_BLOCKS) {
        if (bid == SORT_BLOCKS && tid == 0) {
            out[2 * DISP_ELEMS]     = 0.f;   // trailing zero #1
            out[2 * DISP_ELEMS + 1] = 0.f;   // trailing zero #2
        }
        zfill_loop(o4, &s_chunk);
        __syncthreads();
        if (tid == 0) { __threadfence(); atomicAdd(&g_zdone, 1u); }
        return;
    }

    // ========================== sort blocks ================================
    const int lane = tid & 31;
    const int wid  = tid >> 5;

    // ---- phase 1: logits for this block's 128 tokens (warp-per-token) ----
    // Summation structure (lane-split float4 + shfl tree + s/et) is
    // bit-identical to the prior passing kernel: the FTZ boundary is
    // rank-critical, numerics must not move.
    const float et = expf(temp[0]);
#pragma unroll 1
    for (int pass = 0; pass < 4; ++pass) {
        const int tok = bid * 128 + pass * 32 + wid;   // flat token in [0, B*N)
        float acc[16];
#pragma unroll
        for (int e = 0; e < 16; ++e) acc[e] = 0.0f;

#pragma unroll
        for (int d0 = 0; d0 < DD; d0 += 128) {
            const int d = d0 + lane * 4;
            const float4 kv = *reinterpret_cast<const float4*>(key + (size_t)tok * DD + d);
#pragma unroll
            for (int e = 0; e < 16; ++e) {
                const float4 qv = *reinterpret_cast<const float4*>(query + e * DD + d);
                acc[e] += kv.x * qv.x;  acc[e] += kv.y * qv.y;
                acc[e] += kv.z * qv.z;  acc[e] += kv.w * qv.w;
            }
        }
#pragma unroll
        for (int e = 0; e < 16; ++e) {
            float s = acc[e];
            s += __shfl_xor_sync(0xffffffffu, s, 16);
            s += __shfl_xor_sync(0xffffffffu, s, 8);
            s += __shfl_xor_sync(0xffffffffu, s, 4);
            s += __shfl_xor_sync(0xffffffffu, s, 2);
            s += __shfl_xor_sync(0xffffffffu, s, 1);
            if (lane == e) {
                const int b = tok >> 11;
                const int n = tok & (NN - 1);
                g_logits[(b * EE + e) * NN + n] = s / et;
            }
        }
    }
    __syncthreads();

    // ---- per-batch barrier: wait for the 16 sibling blocks of batch b ----
    const int b  = bid >> 4;
    const int e_ = bid & (EE - 1);
    if (tid == 0) {
        __threadfence();
        atomicAdd(&g_bar_b[b], 1u);
        while (((volatile unsigned*)g_bar_b)[b] < 16u) { }
    }
    __syncthreads();
    __threadfence();

    // ---- phase 2: softmax over tokens (L2 loads; L1 may be stale-free but
    // was never populated with g_logits on this SM -> ldcg is the safe read)
    const float2 v = __ldcg(reinterpret_cast<const float2*>(
                         g_logits + (size_t)bid * NN + 2 * tid));

    float m = fmaxf(v.x, v.y);
#pragma unroll
    for (int s = 16; s > 0; s >>= 1) m = fmaxf(m, __shfl_xor_sync(0xffffffffu, m, s));
    if (lane == 0) red[wid] = m;
    __syncthreads();
    if (wid == 0) {
        float t = red[lane];
#pragma unroll
        for (int s = 16; s > 0; s >>= 1) t = fmaxf(t, __shfl_xor_sync(0xffffffffu, t, s));
        if (lane == 0) red[0] = t;
    }
    __syncthreads();
    m = red[0];
    __syncthreads();

    const float u0 = expf(v.x - m);
    const float u1 = expf(v.y - m);
    float loc = u0 + u1;
#pragma unroll
    for (int s = 16; s > 0; s >>= 1) loc += __shfl_xor_sync(0xffffffffu, loc, s);
    if (lane == 0) red[wid] = loc;
    __syncthreads();
    if (wid == 0) {
        float t = red[lane];
#pragma unroll
        for (int s = 16; s > 0; s >>= 1) t += __shfl_xor_sync(0xffffffffu, t, s);
        if (lane == 0) red[0] = t;
    }
    __syncthreads();
    const float ssum = red[0];

    // affinity (subnormal flush matches the reference's FTZ zero-set) + keys
    float a0 = u0 / ssum;                       // IEEE div (no fast-math)
    float a1 = u1 / ssum;
    if (a0 < FLT_MIN_NORMAL) a0 = 0.0f;
    if (a1 < FLT_MIN_NORMAL) a1 = 0.0f;
    aff[2 * tid]     = a0;
    aff[2 * tid + 1] = a1;
    u64 k0 = ((u64)__float_as_uint(a0) << 32) | (unsigned)(NN - 1 - 2 * tid);
    u64 k1 = ((u64)__float_as_uint(a1) << 32) | (unsigned)(NN - 1 - (2 * tid + 1));

    // ---- phase 3: register-resident bitonic sort (descending) ----
    int pbuf = 0;
    const int i0 = 2 * tid;
    for (int kk = 2; kk <= NN; kk <<= 1) {
        const bool desc = ((i0 & kk) == 0);
        int j = kk >> 1;
        for (; j >= 64; j >>= 1) {              // cross-warp: smem, 1 barrier/pass
            xbuf[pbuf][i0]     = k0;
            xbuf[pbuf][i0 + 1] = k1;
            __syncthreads();
            const u64 p0 = xbuf[pbuf][i0 ^ j];
            const u64 p1 = xbuf[pbuf][(i0 + 1) ^ j];
            const bool low = ((i0 & j) == 0);
            const bool keepmax = (desc == low);
            k0 = keepmax ? (k0 > p0 ? k0 : p0) : (k0 < p0 ? k0 : p0);
            k1 = keepmax ? (k1 > p1 ? k1 : p1) : (k1 < p1 ? k1 : p1);
            pbuf ^= 1;
        }
        for (; j >= 2; j >>= 1) {               // warp-local: shfl
            const int lm = j >> 1;
            const u64 p0 = __shfl_xor_sync(0xffffffffu, k0, lm);
            const u64 p1 = __shfl_xor_sync(0xffffffffu, k1, lm);
            const bool low = ((tid & lm) == 0);
            const bool keepmax = (desc == low);
            k0 = keepmax ? (k0 > p0 ? k0 : p0) : (k0 < p0 ? k0 : p0);
            k1 = keepmax ? (k1 > p1 ? k1 : p1) : (k1 < p1 ? k1 : p1);
        }
        {                                       // j == 1: in-thread
            const u64 mx = k0 > k1 ? k0 : k1;
            const u64 mn = k0 > k1 ? k1 : k0;
            k0 = desc ? mx : mn;
            k1 = desc ? mn : mx;
        }
    }

    // ---- phase 4: help finish the zero-fill (keys live in registers) ----
    zfill_loop(o4, &s_chunk);
    __syncthreads();
    if (tid == 0) {
        __threadfence();
        atomicAdd(&g_zdone, 1u);
        while (((volatile unsigned*)&g_zdone)[0] < (unsigned)GRID_BLOCKS) { }
    }
    __syncthreads();

    // ---- phase 5: scatter hit slots over the (now fully zeroed) output ----
    if (tid < CC / 2) {
        const int tok0 = (NN - 1) - (int)(unsigned)(k0 & 0xffffffffu);
        const int tok1 = (NN - 1) - (int)(unsigned)(k1 & 0xffffffffu);
        const size_t a0i = (((size_t)(b * NN + tok0) * EE) + e_) * CC + (2 * tid);
        const size_t a1i = (((size_t)(b * NN + tok1) * EE) + e_) * CC + (2 * tid + 1);
        out[a0i]              = 1.0f;        // dispatch
        out[DISP_ELEMS + a0i] = aff[tok0];   // combine
        out[a1i]              = 1.0f;
        out[DISP_ELEMS + a1i] = aff[tok1];
    }
}

// ---------------------------------------------------------------------------
extern "C" void kernel_launch(void* const* d_in, const int* in_sizes, int n_in,
                              void* d_out, int out_size)
{
    const float* key   = (const float*)d_in[0];   // [B,N,D]
    const float* query = (const float*)d_in[1];   // [E,D]
    const float* temp  = (const float*)d_in[2];   // scalar log-temp

    (void)in_sizes; (void)n_in; (void)out_size;

    init_kernel<<<1, 32>>>();
    moe_kernel<<<GRID_BLOCKS, THREADS>>>(key, query, temp, (float*)d_out);
}

// round 12
// speedup vs baseline: 3.2527x; 3.2527x over previous
#include <cuda_runtime.h>
#include <math.h>

// Problem constants
#define BB 4
#define NN 2048
#define DD 1024
#define EE 16
#define CC 256
#define BE (BB*EE)                 // 64 (b,e) pairs
#define DISP_ELEMS (BB*NN*EE*CC)   // 33554432 floats per output tensor

#define FLT_MIN_NORMAL 1.17549435e-38f

#define LOGITS_BLOCKS 1024         // every 4th block; 4 warps x 2 tokens = 8 tokens/block
#define ZFILL_BLOCKS  3072
#define TOTAL_BLOCKS  4096
#define OUT_F4 (2 * DISP_ELEMS / 4)   // 16777216 float4 covering both tensors

typedef unsigned long long u64;

// Scratch (no allocations allowed -> __device__ global)
__device__ float g_logits[BE * NN];   // affinity logits (already /exp(temp)), [(b*EE+e)*NN + n]

// ---------------------------------------------------------------------------
// KA: fused gate-logits + output zero-fill, role-interleaved so every wave
// carries both DRAM store traffic (zfill) and FMA work (logits).
//   blockIdx % 4 == 3  -> logits block   (1024 total)
//   else               -> zero-fill block (3072 total)
// ---------------------------------------------------------------------------
__global__ void __launch_bounds__(128)
fused_logits_zfill_kernel(const float* __restrict__ key,
                          const float* __restrict__ query,
                          const float* __restrict__ temp,
                          float* __restrict__ out)
{
    const int tid = threadIdx.x;

    if ((blockIdx.x & 3) != 3) {
        // ---- zero-fill branch: grid-stride streaming float4 stores, 268 MB ----
        const int zb = blockIdx.x - ((blockIdx.x + 1) >> 2);   // dense zfill id [0,3072)
        float4* o4 = reinterpret_cast<float4*>(out);
        const float4 z = make_float4(0.f, 0.f, 0.f, 0.f);
        size_t i = (size_t)zb * 128 + tid;
        const size_t stride = (size_t)ZFILL_BLOCKS * 128;
#pragma unroll 4
        for (; i < OUT_F4; i += stride)
            __stcs(o4 + i, z);
        if (zb == 0 && tid == 0) {
            out[2 * DISP_ELEMS]     = 0.f;   // trailing zero #1
            out[2 * DISP_ELEMS + 1] = 0.f;   // trailing zero #2
        }
        return;
    }

    // ---- logits branch: one warp computes 2 tokens x 16 experts ----
    const int lid  = blockIdx.x >> 2;             // dense logits id [0,1024)
    const int lane = tid & 31;
    const int warp = tid >> 5;
    const int t0   = lid * 8 + warp * 2;          // first of 2 flat tokens in [0, B*N)

    float acc[2][16];
#pragma unroll
    for (int t = 0; t < 2; ++t)
#pragma unroll
        for (int e = 0; e < 16; ++e) acc[t][e] = 0.0f;

#pragma unroll
    for (int d0 = 0; d0 < DD; d0 += 128) {
        const int d = d0 + lane * 4;
        float4 kv0 = __ldcs(reinterpret_cast<const float4*>(key + (size_t)t0 * DD + d));
        float4 kv1 = __ldcs(reinterpret_cast<const float4*>(key + (size_t)(t0 + 1) * DD + d));
#pragma unroll
        for (int e = 0; e < 16; ++e) {
            float4 qv = *reinterpret_cast<const float4*>(query + e * DD + d);
            acc[0][e] += kv0.x * qv.x;  acc[0][e] += kv0.y * qv.y;
            acc[0][e] += kv0.z * qv.z;  acc[0][e] += kv0.w * qv.w;
            acc[1][e] += kv1.x * qv.x;  acc[1][e] += kv1.y * qv.y;
            acc[1][e] += kv1.z * qv.z;  acc[1][e] += kv1.w * qv.w;
        }
    }

    const float et = expf(temp[0]);   // exp(log-temp); divide logits by it

#pragma unroll
    for (int t = 0; t < 2; ++t) {
#pragma unroll
        for (int e = 0; e < 16; ++e) {
            float s = acc[t][e];
            s += __shfl_xor_sync(0xffffffffu, s, 16);
            s += __shfl_xor_sync(0xffffffffu, s, 8);
            s += __shfl_xor_sync(0xffffffffu, s, 4);
            s += __shfl_xor_sync(0xffffffffu, s, 2);
            s += __shfl_xor_sync(0xffffffffu, s, 1);
            if (lane == e) {
                const int tok = t0 + t;
                const int b = tok >> 11;        // / NN
                const int n = tok & (NN - 1);
                g_logits[(b * EE + e) * NN + n] = s / et;
            }
        }
    }
}

// ---------------------------------------------------------------------------
// K2: softmax + top-256 per (b,e) WITHOUT a sort.
// Selection order is bit-equivalent to sorting keys
//     key(n) = (aff_bits(n) << 32) | (2047 - n)        descending
// (aff >= 0 -> float bits monotone; ties -> lower token index first):
//   * nonzero-affinity tokens: slot = #{nonzero keys strictly greater}
//     (keys unique via index bits), selected iff slot < C.
//   * zero-affinity tokens fill remaining slots in ASCENDING token index:
//     token n (zero) gets slot Z + (n - #nonzero_before_n) if < C.
// Affinity FLUSHED TO ZERO below FLT_MIN (normal) to match the reference's
// FTZ zero-set (defines the tie region). Robust for any Z in [0, 2048].
// Scatters directly over the (already zeroed) output.
// ---------------------------------------------------------------------------
__global__ void __launch_bounds__(1024)
topk_scatter_kernel(float* __restrict__ out)
{
    __shared__ float aff[NN];          // 8 KB
    __shared__ u64   list[NN];         // 16 KB compacted nonzero keys (index order)
    __shared__ float red[32];
    __shared__ unsigned warpoff[32];
    __shared__ unsigned s_Z;

    const int tid  = threadIdx.x;
    const int lane = tid & 31;
    const int wid  = tid >> 5;
    const int be   = blockIdx.x;
    const int b    = be >> 4;          // / EE
    const int e    = be & (EE - 1);
    const float* g = g_logits + (size_t)be * NN;

    const int n0 = 2 * tid;
    const int n1 = n0 + 1;

    // load two consecutive tokens per thread (coalesced float2)
    const float2 v = *reinterpret_cast<const float2*>(g + n0);

    // block max
    float m = fmaxf(v.x, v.y);
#pragma unroll
    for (int s = 16; s > 0; s >>= 1) m = fmaxf(m, __shfl_xor_sync(0xffffffffu, m, s));
    if (lane == 0) red[wid] = m;
    __syncthreads();
    if (wid == 0) {
        float t = red[lane];
#pragma unroll
        for (int s = 16; s > 0; s >>= 1) t = fmaxf(t, __shfl_xor_sync(0xffffffffu, t, s));
        if (lane == 0) red[0] = t;
    }
    __syncthreads();
    m = red[0];
    __syncthreads();

    // exp + block sum
    const float u0 = expf(v.x - m);
    const float u1 = expf(v.y - m);
    float loc = u0 + u1;
#pragma unroll
    for (int s = 16; s > 0; s >>= 1) loc += __shfl_xor_sync(0xffffffffu, loc, s);
    if (lane == 0) red[wid] = loc;
    __syncthreads();
    if (wid == 0) {
        float t = red[lane];
#pragma unroll
        for (int s = 16; s > 0; s >>= 1) t += __shfl_xor_sync(0xffffffffu, t, s);
        if (lane == 0) red[0] = t;
    }
    __syncthreads();
    const float ssum = red[0];

    // affinity (with subnormal flush, matching reference FTZ zero-set)
    float a0 = u0 / ssum;                       // IEEE div (no fast-math)
    float a1 = u1 / ssum;
    if (a0 < FLT_MIN_NORMAL) a0 = 0.0f;
    if (a1 < FLT_MIN_NORMAL) a1 = 0.0f;
    aff[n0] = a0;
    aff[n1] = a1;

    // ---- block-wide exclusive prefix sum of nonzero indicator ----
    const int nz0 = (a0 > 0.0f) ? 1 : 0;
    const int nz1 = (a1 > 0.0f) ? 1 : 0;
    const int cnt = nz0 + nz1;

    // warp inclusive scan of per-thread counts
    int inc = cnt;
#pragma unroll
    for (int s = 1; s < 32; s <<= 1) {
        const int p = __shfl_up_sync(0xffffffffu, inc, s);
        if (lane >= s) inc += p;
    }
    if (lane == 31) warpoff[wid] = (unsigned)inc;   // warp total
    __syncthreads();
    if (wid == 0) {
        int t = (int)warpoff[lane];
        int winc = t;
#pragma unroll
        for (int s = 1; s < 32; s <<= 1) {
            const int p = __shfl_up_sync(0xffffffffu, winc, s);
            if (lane >= s) winc += p;
        }
        warpoff[lane] = (unsigned)(winc - t);       // exclusive warp offsets
        if (lane == 31) s_Z = (unsigned)winc;       // total nonzero count
    }
    __syncthreads();

    const int pre0 = (int)warpoff[wid] + (inc - cnt);   // # nonzero tokens before n0
    const int pre1 = pre0 + nz0;                        // ... before n1
    const int Z    = (int)s_Z;

    // compact nonzero keys (index order -> deterministic)
    if (nz0) list[pre0] = ((u64)__float_as_uint(a0) << 32) | (unsigned)(NN - 1 - n0);
    if (nz1) list[pre1] = ((u64)__float_as_uint(a1) << 32) | (unsigned)(NN - 1 - n1);
    __syncthreads();

    // ---- scatter nonzero hits: slot = # strictly-greater nonzero keys ----
    for (int i = tid; i < Z; i += 1024) {
        const u64 ki = list[i];
        int r = 0;
        for (int j = 0; j < Z; ++j)
            r += (list[j] > ki) ? 1 : 0;
        if (r < CC) {
            const int tok = (NN - 1) - (int)(unsigned)(ki & 0xffffffffu);
            const size_t a = (((size_t)(b * NN + tok) * EE) + e) * CC + r;
            out[a]              = 1.0f;        // dispatch
            out[DISP_ELEMS + a] = aff[tok];    // combine (nonzero)
        }
    }

    // ---- zero-affinity fill: slots [Z, CC) by ascending token index ----
    if (Z < CC) {
        const int room = CC - Z;
        if (!nz0) {
            const int pos = n0 - pre0;          // # zero tokens before n0
            if (pos < room) {
                const size_t a = (((size_t)(b * NN + n0) * EE) + e) * CC + (Z + pos);
                out[a] = 1.0f;                  // dispatch; combine stays 0
            }
        }
        if (!nz1) {
            const int pos = n1 - pre1;
            if (pos < room) {
                const size_t a = (((size_t)(b * NN + n1) * EE) + e) * CC + (Z + pos);
                out[a] = 1.0f;
            }
        }
    }
}

// ---------------------------------------------------------------------------
extern "C" void kernel_launch(void* const* d_in, const int* in_sizes, int n_in,
                              void* d_out, int out_size)
{
    const float* key   = (const float*)d_in[0];   // [B,N,D]
    const float* query = (const float*)d_in[1];   // [E,D]
    const float* temp  = (const float*)d_in[2];   // scalar log-temp

    (void)in_sizes; (void)n_in; (void)out_size;

    fused_logits_zfill_kernel<<<TOTAL_BLOCKS, 128>>>(key, query, temp, (float*)d_out);
    topk_scatter_kernel<<<BE, 1024>>>((float*)d_out);
}

// round 16
// speedup vs baseline: 3.3645x; 1.0344x over previous
#include <cuda_runtime.h>
#include <math.h>

// Problem constants
#define BB 4
#define NN 2048
#define DD 1024
#define EE 16
#define CC 256
#define BE (BB*EE)                 // 64 (b,e) pairs
#define DISP_ELEMS (BB*NN*EE*CC)   // 33554432 floats per output tensor

#define FLT_MIN_NORMAL 1.17549435e-38f

// 2:3 interleave -> 2048 logits blocks (1 token/warp, 4 tokens/block) : 3072 zfill
#define LOGITS_BLOCKS 2048
#define ZFILL_BLOCKS  3072
#define TOTAL_BLOCKS  5120
#define OUT_F4 (2 * DISP_ELEMS / 4)   // 16777216 float4 covering both tensors

typedef unsigned long long u64;

// Scratch (no allocations allowed -> __device__ global)
__device__ float g_logits[BE * NN];   // affinity logits (already /exp(temp)), [(b*EE+e)*NN + n]

// ---------------------------------------------------------------------------
// KA: fused gate-logits + output zero-fill, role-interleaved so every wave
// carries both DRAM store traffic (zfill) and FMA work (logits).
//   blockIdx % 5 < 2  -> logits block   (2048 total, warp = 1 token)
//   else              -> zero-fill block (3072 total)
// __launch_bounds__(128, 10): cap regs ~51 so >=10 blocks/SM co-reside ->
// ~40 warps/SM issuing STG.128 (12 cyc/warp issue cost; ~32 warps needed to
// hit the per-SM store budget of ~2.7 f4-stores/cyc).
// ---------------------------------------------------------------------------
__global__ void __launch_bounds__(128, 10)
fused_logits_zfill_kernel(const float* __restrict__ key,
                          const float* __restrict__ query,
                          const float* __restrict__ temp,
                          float* __restrict__ out)
{
    const int tid = threadIdx.x;
    const unsigned q = blockIdx.x / 5u;
    const unsigned r = blockIdx.x % 5u;

    if (r >= 2u) {
        // ---- zero-fill branch: grid-stride streaming float4 stores, 268 MB ----
        const unsigned zb = q * 3u + (r - 2u);     // dense zfill id [0,3072)
        float4* o4 = reinterpret_cast<float4*>(out);
        const float4 z = make_float4(0.f, 0.f, 0.f, 0.f);
        size_t i = (size_t)zb * 128 + tid;
        const size_t stride = (size_t)ZFILL_BLOCKS * 128;
#pragma unroll 4
        for (; i < OUT_F4; i += stride)
            __stcs(o4 + i, z);
        if (zb == 0 && tid == 0) {
            out[2 * DISP_ELEMS]     = 0.f;   // trailing zero #1
            out[2 * DISP_ELEMS + 1] = 0.f;   // trailing zero #2
        }
        return;
    }

    // ---- logits branch: one warp computes 1 token x 16 experts ----
    const unsigned lid = q * 2u + r;              // dense logits id [0,2048)
    const int lane = tid & 31;
    const int warp = tid >> 5;
    const int tok  = (int)lid * 4 + warp;         // flat token in [0, B*N)

    float acc[16];
#pragma unroll
    for (int e = 0; e < 16; ++e) acc[e] = 0.0f;

    // Per-lane accumulation order identical to prior passing kernels:
    // for each d0 sweep, acc[e] += kv.x*qv.x; += y; += z; += w  (serial).
#pragma unroll
    for (int d0 = 0; d0 < DD; d0 += 128) {
        const int d = d0 + lane * 4;
        const float4 kv = __ldcs(reinterpret_cast<const float4*>(key + (size_t)tok * DD + d));
#pragma unroll
        for (int e = 0; e < 16; ++e) {
            const float4 qv = *reinterpret_cast<const float4*>(query + e * DD + d);
            acc[e] += kv.x * qv.x;  acc[e] += kv.y * qv.y;
            acc[e] += kv.z * qv.z;  acc[e] += kv.w * qv.w;
        }
    }

    const float et = expf(temp[0]);   // exp(log-temp); divide logits by it

#pragma unroll
    for (int e = 0; e < 16; ++e) {
        float s = acc[e];
        s += __shfl_xor_sync(0xffffffffu, s, 16);
        s += __shfl_xor_sync(0xffffffffu, s, 8);
        s += __shfl_xor_sync(0xffffffffu, s, 4);
        s += __shfl_xor_sync(0xffffffffu, s, 2);
        s += __shfl_xor_sync(0xffffffffu, s, 1);
        if (lane == e) {
            const int b = tok >> 11;        // / NN
            const int n = tok & (NN - 1);
            g_logits[(b * EE + e) * NN + n] = s / et;
        }
    }
}

// ---------------------------------------------------------------------------
// K2: softmax + top-256 per (b,e) WITHOUT a sort (unchanged from R12 —
// its reduction tree fixes ssum bit-exactly; do not touch).
// Selection order is bit-equivalent to sorting keys
//     key(n) = (aff_bits(n) << 32) | (2047 - n)        descending
//   * nonzero-affinity tokens: slot = #{nonzero keys strictly greater}
//   * zero-affinity tokens fill remaining slots in ASCENDING token index.
// Affinity FLUSHED TO ZERO below FLT_MIN (normal) to match the reference's
// FTZ zero-set. Scatters directly over the (already zeroed) output.
// ---------------------------------------------------------------------------
__global__ void __launch_bounds__(1024)
topk_scatter_kernel(float* __restrict__ out)
{
    __shared__ float aff[NN];          // 8 KB
    __shared__ u64   list[NN];         // 16 KB compacted nonzero keys (index order)
    __shared__ float red[32];
    __shared__ unsigned warpoff[32];
    __shared__ unsigned s_Z;

    const int tid  = threadIdx.x;
    const int lane = tid & 31;
    const int wid  = tid >> 5;
    const int be   = blockIdx.x;
    const int b    = be >> 4;          // / EE
    const int e    = be & (EE - 1);
    const float* g = g_logits + (size_t)be * NN;

    const int n0 = 2 * tid;
    const int n1 = n0 + 1;

    // load two consecutive tokens per thread (coalesced float2)
    const float2 v = *reinterpret_cast<const float2*>(g + n0);

    // block max
    float m = fmaxf(v.x, v.y);
#pragma unroll
    for (int s = 16; s > 0; s >>= 1) m = fmaxf(m, __shfl_xor_sync(0xffffffffu, m, s));
    if (lane == 0) red[wid] = m;
    __syncthreads();
    if (wid == 0) {
        float t = red[lane];
#pragma unroll
        for (int s = 16; s > 0; s >>= 1) t = fmaxf(t, __shfl_xor_sync(0xffffffffu, t, s));
        if (lane == 0) red[0] = t;
    }
    __syncthreads();
    m = red[0];
    __syncthreads();

    // exp + block sum
    const float u0 = expf(v.x - m);
    const float u1 = expf(v.y - m);
    float loc = u0 + u1;
#pragma unroll
    for (int s = 16; s > 0; s >>= 1) loc += __shfl_xor_sync(0xffffffffu, loc, s);
    if (lane == 0) red[wid] = loc;
    __syncthreads();
    if (wid == 0) {
        float t = red[lane];
#pragma unroll
        for (int s = 16; s > 0; s >>= 1) t += __shfl_xor_sync(0xffffffffu, t, s);
        if (lane == 0) red[0] = t;
    }
    __syncthreads();
    const float ssum = red[0];

    // affinity (with subnormal flush, matching reference FTZ zero-set)
    float a0 = u0 / ssum;                       // IEEE div (no fast-math)
    float a1 = u1 / ssum;
    if (a0 < FLT_MIN_NORMAL) a0 = 0.0f;
    if (a1 < FLT_MIN_NORMAL) a1 = 0.0f;
    aff[n0] = a0;
    aff[n1] = a1;

    // ---- block-wide exclusive prefix sum of nonzero indicator ----
    const int nz0 = (a0 > 0.0f) ? 1 : 0;
    const int nz1 = (a1 > 0.0f) ? 1 : 0;
    const int cnt = nz0 + nz1;

    int inc = cnt;
#pragma unroll
    for (int s = 1; s < 32; s <<= 1) {
        const int p = __shfl_up_sync(0xffffffffu, inc, s);
        if (lane >= s) inc += p;
    }
    if (lane == 31) warpoff[wid] = (unsigned)inc;   // warp total
    __syncthreads();
    if (wid == 0) {
        int t = (int)warpoff[lane];
        int winc = t;
#pragma unroll
        for (int s = 1; s < 32; s <<= 1) {
            const int p = __shfl_up_sync(0xffffffffu, winc, s);
            if (lane >= s) winc += p;
        }
        warpoff[lane] = (unsigned)(winc - t);       // exclusive warp offsets
        if (lane == 31) s_Z = (unsigned)winc;       // total nonzero count
    }
    __syncthreads();

    const int pre0 = (int)warpoff[wid] + (inc - cnt);   // # nonzero tokens before n0
    const int pre1 = pre0 + nz0;                        // ... before n1
    const int Z    = (int)s_Z;

    // compact nonzero keys (index order -> deterministic)
    if (nz0) list[pre0] = ((u64)__float_as_uint(a0) << 32) | (unsigned)(NN - 1 - n0);
    if (nz1) list[pre1] = ((u64)__float_as_uint(a1) << 32) | (unsigned)(NN - 1 - n1);
    __syncthreads();

    // ---- scatter nonzero hits: slot = # strictly-greater nonzero keys ----
    for (int i = tid; i < Z; i += 1024) {
        const u64 ki = list[i];
        int rk = 0;
        for (int j = 0; j < Z; ++j)
            rk += (list[j] > ki) ? 1 : 0;
        if (rk < CC) {
            const int tok = (NN - 1) - (int)(unsigned)(ki & 0xffffffffu);
            const size_t a = (((size_t)(b * NN + tok) * EE) + e) * CC + rk;
            out[a]              = 1.0f;        // dispatch
            out[DISP_ELEMS + a] = aff[tok];    // combine (nonzero)
        }
    }

    // ---- zero-affinity fill: slots [Z, CC) by ascending token index ----
    if (Z < CC) {
        const int room = CC - Z;
        if (!nz0) {
            const int pos = n0 - pre0;          // # zero tokens before n0
            if (pos < room) {
                const size_t a = (((size_t)(b * NN + n0) * EE) + e) * CC + (Z + pos);
                out[a] = 1.0f;                  // dispatch; combine stays 0
            }
        }
        if (!nz1) {
            const int pos = n1 - pre1;
            if (pos < room) {
                const size_t a = (((size_t)(b * NN + n1) * EE) + e) * CC + (Z + pos);
                out[a] = 1.0f;
            }
        }
    }
}

// ---------------------------------------------------------------------------
extern "C" void kernel_launch(void* const* d_in, const int* in_sizes, int n_in,
                              void* d_out, int out_size)
{
    const float* key   = (const float*)d_in[0];   // [B,N,D]
    const float* query = (const float*)d_in[1];   // [E,D]
    const float* temp  = (const float*)d_in[2];   // scalar log-temp

    (void)in_sizes; (void)n_in; (void)out_size;

    fused_logits_zfill_kernel<<<TOTAL_BLOCKS, 128>>>(key, query, temp, (float*)d_out);
    topk_scatter_kernel<<<BE, 1024>>>((float*)d_out);
}